// round 1
// baseline (speedup 1.0000x reference)
#include <cuda_runtime.h>

#define TX 32
#define TY 32
#define BDX 32
#define BDY 8
#define NTHREADS (BDX * BDY)
#define EPS 1e-8f

// Fused learnable demosaick:
//  1) load mosaick tile (+2 halo, edge-clamped) into smem
//  2) compute green tile (+1 halo) into smem
//  3) 3x3 chroma-difference interpolation -> write R,G,B
__global__ __launch_bounds__(NTHREADS) void demosaick_kernel(
    const float* __restrict__ m,
    const float* __restrict__ gfilt,
    const float* __restrict__ grad_filt,
    float* __restrict__ out,
    int H, int W)
{
    __shared__ float sm[TY + 4][TX + 4];   // mosaick tile, halo 2
    __shared__ float sg[TY + 2][TX + 2];   // green tile, halo 1

    const int bx0 = blockIdx.x * TX;
    const int by0 = blockIdx.y * TY;
    const int b   = blockIdx.z;

    const float* __restrict__ mb = m + (size_t)b * H * W;
    const int tid = threadIdx.y * BDX + threadIdx.x;

    const float gf0 = gfilt[0], gf1 = gfilt[1], gf2 = gfilt[2];
    const float r0  = grad_filt[0], r1 = grad_filt[1], r2 = grad_filt[2];

    // ---- load mosaick tile with edge clamping (matches jnp.pad mode='edge') ----
    #pragma unroll
    for (int idx = tid; idx < (TY + 4) * (TX + 4); idx += NTHREADS) {
        int j = idx / (TX + 4);
        int i = idx - j * (TX + 4);
        int gy = by0 - 2 + j;
        int gx = bx0 - 2 + i;
        gy = min(max(gy, 0), H - 1);
        gx = min(max(gx, 0), W - 1);
        sm[j][i] = mb[(size_t)gy * W + gx];
    }
    __syncthreads();

    // ---- compute green tile (valid only where the global coord is in-image;
    //      out-of-image halo entries are never consumed thanks to the bounds
    //      check in the chroma loop) ----
    #pragma unroll
    for (int idx = tid; idx < (TY + 2) * (TX + 2); idx += NTHREADS) {
        int j = idx / (TX + 2);
        int i = idx - j * (TX + 2);
        float c  = sm[j + 1][i + 1];
        float xl = sm[j + 1][i];
        float xr = sm[j + 1][i + 2];
        float yu = sm[j][i + 1];
        float yd = sm[j + 2][i + 1];

        float gh = gf0 * xl + gf1 * c + gf2 * xr;
        float gv = gf0 * yu + gf1 * c + gf2 * yd;
        float dx = r0  * xl + r1  * c + r2  * xr;
        float dy = r0  * yu + r1  * c + r2  * yd;

        float adx = fabsf(dx), ady = fabsf(dy);
        float w   = ady / (adx + ady + EPS);
        float gi  = w * gh + (1.0f - w) * gv;

        int gy = by0 - 1 + j;
        int gx = bx0 - 1 + i;
        bool isg = ((gx & 1) == (gy & 1));   // sign bits irrelevant for unused halo
        sg[j][i] = isg ? c : gi;
    }
    __syncthreads();

    // ---- 3x3 chroma interpolation + output ----
    const float Kw[3][3] = {{0.25f, 0.5f, 0.25f},
                            {0.5f,  1.0f, 0.5f },
                            {0.25f, 0.5f, 0.25f}};

    const int tx = threadIdx.x;
    const size_t img = (size_t)H * W;
    float* __restrict__ out_r = out + (size_t)(b * 3 + 0) * img;
    float* __restrict__ out_g = out + (size_t)(b * 3 + 1) * img;
    float* __restrict__ out_b = out + (size_t)(b * 3 + 2) * img;

    #pragma unroll
    for (int rr = 0; rr < TY / BDY; ++rr) {
        const int ty = threadIdx.y + rr * BDY;
        const int y  = by0 + ty;
        const int x  = bx0 + tx;
        if (y >= H || x >= W) continue;

        const float g = sg[ty + 1][tx + 1];

        float num_r = 0.f, den_r = 0.f, num_b = 0.f, den_b = 0.f;
        #pragma unroll
        for (int dy = -1; dy <= 1; ++dy) {
            #pragma unroll
            for (int dx = -1; dx <= 1; ++dx) {
                int yy = y + dy, xx = x + dx;
                // zero-padded SAME conv: out-of-image contributes nothing
                if (yy < 0 || yy >= H || xx < 0 || xx >= W) continue;
                float kw   = Kw[dy + 1][dx + 1];
                float diff = sm[ty + 2 + dy][tx + 2 + dx] - sg[ty + 1 + dy][tx + 1 + dx];
                bool is_r = ((yy & 1) == 0) & ((xx & 1) == 1);
                bool is_b = ((yy & 1) == 1) & ((xx & 1) == 0);
                if (is_r) { num_r += kw * diff; den_r += kw; }
                if (is_b) { num_b += kw * diff; den_b += kw; }
            }
        }

        const size_t o = (size_t)y * W + x;
        out_r[o] = g + num_r / (den_r + EPS);
        out_g[o] = g;
        out_b[o] = g + num_b / (den_b + EPS);
    }
}

extern "C" void kernel_launch(void* const* d_in, const int* in_sizes, int n_in,
                              void* d_out, int out_size)
{
    const float* m         = (const float*)d_in[0];
    const float* gfilt     = (const float*)d_in[1];
    const float* grad_filt = (const float*)d_in[2];
    float* out             = (float*)d_out;

    const int H = 1024, W = 1024;
    const int B = in_sizes[0] / (H * W);

    dim3 block(BDX, BDY);
    dim3 grid(W / TX, H / TY, B);
    demosaick_kernel<<<grid, block>>>(m, gfilt, grad_filt, out, H, W);
}

// round 2
// speedup vs baseline: 1.6265x; 1.6265x over previous
#include <cuda_runtime.h>

#define TX 128
#define TY 16
#define BDX 32
#define BDY 8
#define NTHREADS 256
#define SMW 136            // mosaick tile width: halo 4 each side (16B aligned)
#define SMH (TY + 4)       // 20
#define SGW 136            // green tile width (same indexing as sm)
#define SGH (TY + 2)       // 18
#define EPS 1e-8f

// Fused learnable demosaick, parity-specialized fast path.
//  smem index convention: column i <-> global x = bx0 + i - 4
//                         sm row r <-> global y = by0 + r - 2
//                         sg row j <-> global y = by0 + j - 1
__global__ __launch_bounds__(NTHREADS) void demosaick_kernel(
    const float* __restrict__ m,
    const float* __restrict__ gfilt,
    const float* __restrict__ grad_filt,
    float* __restrict__ out,
    int H, int W)
{
    __shared__ __align__(16) float sm[SMH][SMW];
    __shared__ __align__(16) float sg[SGH][SGW];

    const int bx0 = blockIdx.x * TX;
    const int by0 = blockIdx.y * TY;
    const int b   = blockIdx.z;
    const float* __restrict__ mb = m + (size_t)b * H * W;
    const int tid = threadIdx.y * BDX + threadIdx.x;

    const float gf0 = gfilt[0], gf1 = gfilt[1], gf2 = gfilt[2];
    const float r0  = grad_filt[0], r1 = grad_filt[1], r2 = grad_filt[2];

    // ---------------- tile load (edge-clamped == jnp.pad mode='edge') --------
    const bool xint = (bx0 > 0) && (bx0 + TX < W);
    if (xint) {
        #pragma unroll
        for (int idx = tid; idx < SMH * (SMW / 4); idx += NTHREADS) {
            int row = idx / (SMW / 4);
            int q   = idx - row * (SMW / 4);
            int gy  = min(max(by0 - 2 + row, 0), H - 1);
            float4 v = *reinterpret_cast<const float4*>(
                &mb[(size_t)gy * W + (bx0 - 4 + 4 * q)]);
            *reinterpret_cast<float4*>(&sm[row][4 * q]) = v;
        }
    } else {
        for (int idx = tid; idx < SMH * SMW; idx += NTHREADS) {
            int row = idx / SMW;
            int i   = idx - row * SMW;
            int gy  = min(max(by0 - 2 + row, 0), H - 1);
            int gx  = min(max(bx0 - 4 + i, 0), W - 1);
            sm[row][i] = mb[(size_t)gy * W + gx];
        }
    }
    __syncthreads();

    // ---------------- green fill: pairs (one copy at g-site, one interp) -----
    // sites: rows j in [0,SGH), cols i in [3,133) -> 65 pairs per row
    {
        const int NP = SGH * 65;
        for (int idx = tid; idx < NP; idx += NTHREADS) {
            int j  = idx / 65;
            int p  = idx - j * 65;
            int i0 = 3 + 2 * p;            // global x parity: odd
            int gy = by0 - 1 + j;
            int par = gy & 1;              // works for gy = -1 too
            int ing = i0 + par;            // non-green site (interp)
            int icp = i0 + 1 - par;        // green site (copy)

            sg[j][icp] = sm[j + 1][icp];

            float c  = sm[j + 1][ing];
            float xl = sm[j + 1][ing - 1];
            float xr = sm[j + 1][ing + 1];
            float yu = sm[j][ing];
            float yd = sm[j + 2][ing];

            float gh = gf0 * xl + gf1 * c + gf2 * xr;
            float gv = gf0 * yu + gf1 * c + gf2 * yd;
            float dx = r0 * xl + r1 * c + r2 * xr;
            float dy = r0 * yu + r1 * c + r2 * yd;

            float adx = fabsf(dx), ady = fabsf(dy);
            float w  = __fdividef(ady, adx + ady + EPS);
            sg[j][ing] = w * gh + (1.0f - w) * gv;
        }
    }
    __syncthreads();

    // ---------------- chroma + output ----------------------------------------
    const size_t img = (size_t)H * W;
    float* __restrict__ outr = out + (size_t)(b * 3 + 0) * img;
    float* __restrict__ outg = out + (size_t)(b * 3 + 1) * img;
    float* __restrict__ outb = out + (size_t)(b * 3 + 2) * img;

    const int lx0 = threadIdx.x * 4;
    const int x0  = bx0 + lx0;
    const int cb  = lx0 + 4;      // smem column of pixel x0

    #pragma unroll
    for (int rr = 0; rr < TY / BDY; ++rr) {
        const int ty   = threadIdx.y + rr * BDY;
        const int y    = by0 + ty;
        const int srow = ty + 1;   // sg row of this pixel row
        const int mrow = ty + 2;   // sm row of this pixel row
        const size_t o = (size_t)y * W + x0;

        const bool fast = (y > 0) & (y < H - 1) & (x0 > 0) & (x0 < W - 4);
        if (fast) {
            float4 g4 = *reinterpret_cast<const float4*>(&sg[srow][cb]);
            float4 R, Bv;
            if ((y & 1) == 0) {
                // classes: G R G R
                float m1 = sm[mrow][cb + 1], m3 = sm[mrow][cb + 3];
                float hA = sm[mrow][cb - 1] - sg[srow][cb - 1];
                float hB = m1 - g4.y;
                float hC = m3 - g4.w;
                float vU0 = sm[mrow - 1][cb]     - sg[srow - 1][cb];
                float vU2 = sm[mrow - 1][cb + 2] - sg[srow - 1][cb + 2];
                float vU4 = sm[mrow - 1][cb + 4] - sg[srow - 1][cb + 4];
                float vD0 = sm[mrow + 1][cb]     - sg[srow + 1][cb];
                float vD2 = sm[mrow + 1][cb + 2] - sg[srow + 1][cb + 2];
                float vD4 = sm[mrow + 1][cb + 4] - sg[srow + 1][cb + 4];
                R.x  = g4.x + 0.5f  * (hA + hB);
                R.y  = g4.y + hB;
                R.z  = g4.z + 0.5f  * (hB + hC);
                R.w  = g4.w + hC;
                Bv.x = g4.x + 0.5f  * (vU0 + vD0);
                Bv.y = g4.y + 0.25f * (vU0 + vU2 + vD0 + vD2);
                Bv.z = g4.z + 0.5f  * (vU2 + vD2);
                Bv.w = g4.w + 0.25f * (vU2 + vU4 + vD2 + vD4);
            } else {
                // classes: B G B G
                float m0 = sm[mrow][cb], m2 = sm[mrow][cb + 2];
                float h0 = m0 - g4.x;
                float h2 = m2 - g4.z;
                float h4 = sm[mrow][cb + 4] - sg[srow][cb + 4];
                float vUa = sm[mrow - 1][cb - 1] - sg[srow - 1][cb - 1];
                float vUb = sm[mrow - 1][cb + 1] - sg[srow - 1][cb + 1];
                float vUc = sm[mrow - 1][cb + 3] - sg[srow - 1][cb + 3];
                float vDa = sm[mrow + 1][cb - 1] - sg[srow + 1][cb - 1];
                float vDb = sm[mrow + 1][cb + 1] - sg[srow + 1][cb + 1];
                float vDc = sm[mrow + 1][cb + 3] - sg[srow + 1][cb + 3];
                Bv.x = g4.x + h0;
                Bv.y = g4.y + 0.5f  * (h0 + h2);
                Bv.z = g4.z + h2;
                Bv.w = g4.w + 0.5f  * (h2 + h4);
                R.x  = g4.x + 0.25f * (vUa + vUb + vDa + vDb);
                R.y  = g4.y + 0.5f  * (vUb + vDb);
                R.z  = g4.z + 0.25f * (vUb + vUc + vDb + vDc);
                R.w  = g4.w + 0.5f  * (vUc + vDc);
            }
            *reinterpret_cast<float4*>(&outr[o]) = R;
            *reinterpret_cast<float4*>(&outg[o]) = g4;
            *reinterpret_cast<float4*>(&outb[o]) = Bv;
        } else {
            // generic bounds-checked path (boundary ring only)
            #pragma unroll
            for (int k = 0; k < 4; ++k) {
                int x = x0 + k;
                float g = sg[srow][cb + k];
                float nr = 0.f, dr = 0.f, nb = 0.f, db = 0.f;
                #pragma unroll
                for (int dyy = -1; dyy <= 1; ++dyy) {
                    #pragma unroll
                    for (int dxx = -1; dxx <= 1; ++dxx) {
                        int yy = y + dyy, xx = x + dxx;
                        if (yy < 0 || yy >= H || xx < 0 || xx >= W) continue;
                        float kw = 0.25f * (float)((2 - abs(dyy)) * (2 - abs(dxx)));
                        float diff = sm[mrow + dyy][cb + k + dxx]
                                   - sg[srow + dyy][cb + k + dxx];
                        bool isr = ((yy & 1) == 0) & ((xx & 1) == 1);
                        bool isb = ((yy & 1) == 1) & ((xx & 1) == 0);
                        if (isr) { nr += kw * diff; dr += kw; }
                        if (isb) { nb += kw * diff; db += kw; }
                    }
                }
                outr[o + k] = g + nr / (dr + EPS);
                outg[o + k] = g;
                outb[o + k] = g + nb / (db + EPS);
            }
        }
    }
}

extern "C" void kernel_launch(void* const* d_in, const int* in_sizes, int n_in,
                              void* d_out, int out_size)
{
    const float* m         = (const float*)d_in[0];
    const float* gfilt     = (const float*)d_in[1];
    const float* grad_filt = (const float*)d_in[2];
    float* out             = (float*)d_out;

    const int H = 1024, W = 1024;
    const int B = in_sizes[0] / (H * W);

    dim3 block(BDX, BDY);
    dim3 grid(W / TX, H / TY, B);
    demosaick_kernel<<<grid, block>>>(m, gfilt, grad_filt, out, H, W);
}

// round 3
// speedup vs baseline: 2.2079x; 1.3574x over previous
#include <cuda_runtime.h>

#define TX 128
#define TY 16
#define NTHREADS 256
#define SMW 136            // mosaick tile width: halo 4 each side (16B aligned)
#define SMH (TY + 4)       // 20
#define SDW 68             // parity-packed diff width
#define SDH (TY + 2)       // 18
#define EPS 1e-8f

// Fused learnable demosaick.
//  sm column i  <-> global x = bx0 + i - 4   (bx0-4 is even, so parity(x)=parity(i))
//  sm row    r  <-> global y = by0 + r - 2
//  sd row    j  <-> global y = by0 + j - 1
//  sd[j][k] = (m - g_interp) at non-green site i = 2*k + pr, pr = 1 - (y&1)
__global__ __launch_bounds__(NTHREADS) void demosaick_kernel(
    const float* __restrict__ m,
    const float* __restrict__ gfilt,
    const float* __restrict__ grad_filt,
    float* __restrict__ out,
    int H, int W)
{
    __shared__ __align__(16) float sm[SMH][SMW];
    __shared__ __align__(16) float sd[SDH][SDW];

    const int bx0 = blockIdx.x * TX;
    const int by0 = blockIdx.y * TY;
    const int b   = blockIdx.z;
    const float* __restrict__ mb = m + (size_t)b * H * W;
    const int tid = threadIdx.x;

    const float gf0 = gfilt[0], gf1 = gfilt[1], gf2 = gfilt[2];
    const float r0  = grad_filt[0], r1 = grad_filt[1], r2 = grad_filt[2];

    // ---------------- tile load (edge-clamped == jnp.pad mode='edge') --------
    if ((bx0 > 0) && (bx0 + TX < W)) {
        #pragma unroll
        for (int idx = tid; idx < SMH * (SMW / 4); idx += NTHREADS) {
            int row = idx / (SMW / 4);
            int q   = idx - row * (SMW / 4);
            int gy  = min(max(by0 - 2 + row, 0), H - 1);
            float4 v = *reinterpret_cast<const float4*>(
                &mb[(size_t)gy * W + (bx0 - 4 + 4 * q)]);
            *reinterpret_cast<float4*>(&sm[row][4 * q]) = v;
        }
    } else {
        for (int idx = tid; idx < SMH * SMW; idx += NTHREADS) {
            int row = idx / SMW;
            int i   = idx - row * SMW;
            int gy  = min(max(by0 - 2 + row, 0), H - 1);
            int gx  = min(max(bx0 - 4 + i, 0), W - 1);
            sm[row][i] = mb[(size_t)gy * W + gx];
        }
    }
    __syncthreads();

    // ---------------- diff fill: sd = m - g_interp at non-green sites --------
    {
        const int NP = SDH * 66;
        for (int idx = tid; idx < NP; idx += NTHREADS) {
            int j  = idx / 66;
            int kk = idx - j * 66 + 1;         // k in [1,66]
            int y  = by0 - 1 + j;
            int pr = 1 - (y & 1);              // non-green column parity
            int i  = 2 * kk + pr;              // i in [2,134]

            float c  = sm[j + 1][i];
            float xl = sm[j + 1][i - 1];
            float xr = sm[j + 1][i + 1];
            float yu = sm[j][i];
            float yd = sm[j + 2][i];

            float gh = gf0 * xl + gf1 * c + gf2 * xr;
            float gv = gf0 * yu + gf1 * c + gf2 * yd;
            float dx = r0 * xl + r1 * c + r2 * xr;
            float dy = r0 * yu + r1 * c + r2 * yd;

            float adx = fabsf(dx), ady = fabsf(dy);
            float w   = __fdividef(ady, adx + ady + EPS);
            float gi  = w * gh + (1.0f - w) * gv;
            sd[j][kk] = c - gi;
        }
    }
    __syncthreads();

    // ---------------- chroma + output: 2 px/thread, stride-1 sd reads --------
    const size_t img = (size_t)H * W;
    float* __restrict__ outr = out + (size_t)(b * 3 + 0) * img;
    float* __restrict__ outg = out + (size_t)(b * 3 + 1) * img;
    float* __restrict__ outb = out + (size_t)(b * 3 + 2) * img;

    const int c  = tid & 63;           // pair column
    const int g2 = tid >> 6;           // row group (0..3)
    const int x0 = bx0 + 2 * c;
    const int cb = 2 * c + 4;          // sm column of pixel x0

    #pragma unroll
    for (int rr = 0; rr < 4; ++rr) {
        const int ty = g2 * 4 + rr;
        const int y  = by0 + ty;
        const size_t o = (size_t)y * W + x0;

        const bool fast = (y > 0) & (y < H - 1) & (x0 > 0) & (x0 < W - 2);
        if (fast) {
            float2 m2 = *reinterpret_cast<const float2*>(&sm[ty + 2][cb]);
            float2 G, R, Bv;
            if ((y & 1) == 0) {
                // classes: G R   (own row pr=1; up/down rows pr=0)
                float dLo = sd[ty + 1][c + 1];      // i = cb-1
                float dCo = sd[ty + 1][c + 2];      // i = cb+1
                float du0 = sd[ty][c + 2];          // i = cb
                float du2 = sd[ty][c + 3];          // i = cb+2
                float dd0 = sd[ty + 2][c + 2];
                float dd2 = sd[ty + 2][c + 3];
                G.x  = m2.x;
                G.y  = m2.y - dCo;
                R.x  = G.x + 0.5f * (dLo + dCo);
                R.y  = m2.y;                         // red at R-site = mosaick
                Bv.x = G.x + 0.5f  * (du0 + dd0);
                Bv.y = G.y + 0.25f * (du0 + du2 + dd0 + dd2);
            } else {
                // classes: B G   (own row pr=0; up/down rows pr=1)
                float d0  = sd[ty + 1][c + 2];      // i = cb
                float d2  = sd[ty + 1][c + 3];      // i = cb+2
                float dua = sd[ty][c + 1];          // i = cb-1
                float dub = sd[ty][c + 2];          // i = cb+1
                float dda = sd[ty + 2][c + 1];
                float ddb = sd[ty + 2][c + 2];
                G.x  = m2.x - d0;
                G.y  = m2.y;
                Bv.x = m2.x;                         // blue at B-site = mosaick
                Bv.y = G.y + 0.5f  * (d0 + d2);
                R.x  = G.x + 0.25f * (dua + dub + dda + ddb);
                R.y  = G.y + 0.5f  * (dub + ddb);
            }
            *reinterpret_cast<float2*>(&outr[o]) = R;
            *reinterpret_cast<float2*>(&outg[o]) = G;
            *reinterpret_cast<float2*>(&outb[o]) = Bv;
        } else {
            // generic bounds-checked path (boundary ring only)
            #pragma unroll
            for (int kk = 0; kk < 2; ++kk) {
                int x = x0 + kk;
                int ii = cb + kk;
                float mv = sm[ty + 2][ii];
                bool isg = ((x & 1) == (y & 1));
                int pro  = 1 - (y & 1);
                float g  = isg ? mv : mv - sd[ty + 1][(ii - pro) >> 1];

                float nr = 0.f, dr = 0.f, nb = 0.f, db = 0.f;
                #pragma unroll
                for (int dyy = -1; dyy <= 1; ++dyy) {
                    #pragma unroll
                    for (int dxx = -1; dxx <= 1; ++dxx) {
                        int yy = y + dyy, xx = x + dxx;
                        if (yy < 0 || yy >= H || xx < 0 || xx >= W) continue;
                        bool isr = ((yy & 1) == 0) & ((xx & 1) == 1);
                        bool isb = ((yy & 1) == 1) & ((xx & 1) == 0);
                        if (isr | isb) {
                            float kw = 0.25f * (float)((2 - abs(dyy)) * (2 - abs(dxx)));
                            int prr  = 1 - (yy & 1);
                            float d  = sd[ty + 1 + dyy][(ii + dxx - prr) >> 1];
                            if (isr) { nr += kw * d; dr += kw; }
                            else     { nb += kw * d; db += kw; }
                        }
                    }
                }
                outr[o + kk] = g + nr / (dr + EPS);
                outg[o + kk] = g;
                outb[o + kk] = g + nb / (db + EPS);
            }
        }
    }
}

extern "C" void kernel_launch(void* const* d_in, const int* in_sizes, int n_in,
                              void* d_out, int out_size)
{
    const float* m         = (const float*)d_in[0];
    const float* gfilt     = (const float*)d_in[1];
    const float* grad_filt = (const float*)d_in[2];
    float* out             = (float*)d_out;

    const int H = 1024, W = 1024;
    const int B = in_sizes[0] / (H * W);

    dim3 block(NTHREADS);
    dim3 grid(W / TX, H / TY, B);
    demosaick_kernel<<<grid, block>>>(m, gfilt, grad_filt, out, H, W);
}